// round 5
// baseline (speedup 1.0000x reference)
#include <cuda_runtime.h>

#define BATCH 8
#define NPTS  8192
#define NS    2048      // S = 0.25 * N
#define KNB   32        // nsample
#define C1    64
#define C2    64
#define C3    128

#define NCONS        139                  // consumer CTAs (persistent)
#define CONS_THREADS 384
#define CONS_WARPS   (NCONS * 12)         // 1668
#define NITEMS       (BATCH * NS)         // 16384

// scratch shared between producer (FPS) and consumer (ball-query+MLP) CTAs
__device__ float g_new_xyz[BATCH * NS * 3];
__device__ int   g_prog[BATCH * 32];      // padded: one 128B line per batch

// XLA-exact squared distance: ((dx*dx + dy*dy) + dz*dz), no FMA contraction
__device__ __forceinline__ float sqdist_xla(float dx, float dy, float dz) {
    return __fadd_rn(__fadd_rn(__fmul_rn(dx, dx), __fmul_rn(dy, dy)),
                     __fmul_rn(dz, dz));
}

__device__ __forceinline__ unsigned long long pack2(float a, float b) {
    unsigned long long r;
    asm("mov.b64 %0, {%1, %2};" : "=l"(r) : "f"(a), "f"(b));
    return r;
}
__device__ __forceinline__ void unpack2(unsigned long long v, float& a, float& b) {
    asm("mov.b64 {%0, %1}, %2;" : "=f"(a), "=f"(b) : "l"(v));
}
__device__ __forceinline__ unsigned long long add2(unsigned long long a, unsigned long long b) {
    unsigned long long r;
    asm("add.rn.f32x2 %0, %1, %2;" : "=l"(r) : "l"(a), "l"(b));
    return r;
}
__device__ __forceinline__ unsigned long long mul2(unsigned long long a, unsigned long long b) {
    unsigned long long r;
    asm("mul.rn.f32x2 %0, %1, %2;" : "=l"(r) : "l"(a), "l"(b));
    return r;
}
__device__ __forceinline__ unsigned long long fma2(unsigned long long a, unsigned long long b,
                                                   unsigned long long c) {
    unsigned long long r;
    asm("fma.rn.f32x2 %0, %1, %2, %3;" : "=l"(r) : "l"(a), "l"(b), "l"(c));
    return r;
}

__global__ void reset_kernel() {
    if (threadIdx.x < BATCH) g_prog[threadIdx.x * 32] = 0;
}

// ---------------------------------------------------------------------------
// Producer: farthest point sampling for batch b. Runs on 256 threads (warps
// 8..11 of the CTA have exited). Bit-exact math (f32x2, per-lane rn).
// After writing center s, releases g_prog[b*32] = s+1.
// ---------------------------------------------------------------------------
__device__ void fps_producer(const float* __restrict__ xyz,
                             float* __restrict__ out, int b)
{
    const int tid = threadIdx.x;
    const int lane = tid & 31, wid = tid >> 5;
    const float* P = xyz + b * NPTS * 3;

    __shared__ float sV[2][8];
    __shared__ int   sI[2][8];

    unsigned long long npx[16], npy[16], npz[16];
    float dist[32];
#pragma unroll
    for (int m = 0; m < 16; m++) {
        int i0 = tid + (2 * m) * 256;
        int i1 = tid + (2 * m + 1) * 256;
        npx[m] = pack2(-P[i0 * 3 + 0], -P[i1 * 3 + 0]);
        npy[m] = pack2(-P[i0 * 3 + 1], -P[i1 * 3 + 1]);
        npz[m] = pack2(-P[i0 * 3 + 2], -P[i1 * 3 + 2]);
        dist[2 * m] = 1e10f;
        dist[2 * m + 1] = 1e10f;
    }
    float cx = __ldg(P + 0), cy = __ldg(P + 1), cz = __ldg(P + 2);

    for (int s = 0; s < NS; s++) {
        if (tid == 0) {
            int o = b * 3 * NS + s;          // (B,3,S) transposed output
            out[o]          = cx;
            out[o + NS]     = cy;
            out[o + 2 * NS] = cz;
            int c = (b * NS + s) * 3;
            g_new_xyz[c]     = cx;
            g_new_xyz[c + 1] = cy;
            g_new_xyz[c + 2] = cz;
            // publish: release orders the 6 stores above before the flag
            asm volatile("st.release.gpu.global.s32 [%0], %1;"
                         :: "l"(&g_prog[b * 32]), "r"(s + 1) : "memory");
        }

        const unsigned long long cxx = pack2(cx, cx);
        const unsigned long long cyy = pack2(cy, cy);
        const unsigned long long czz = pack2(cz, cz);

        float bv = -1.0f;
        int   bi = 0;
#pragma unroll
        for (int m = 0; m < 16; m++) {
            unsigned long long dx2 = add2(cxx, npx[m]);   // cx - px (exact)
            unsigned long long dy2 = add2(cyy, npy[m]);
            unsigned long long dz2 = add2(czz, npz[m]);
            unsigned long long d2p = add2(add2(mul2(dx2, dx2), mul2(dy2, dy2)),
                                          mul2(dz2, dz2)); // ((x²+y²)+z²) rn
            float d0, d1;
            unpack2(d2p, d0, d1);
            float nd0 = fminf(dist[2 * m], d0);
            dist[2 * m] = nd0;
            if (nd0 > bv) { bv = nd0; bi = tid + (2 * m) * 256; }
            float nd1 = fminf(dist[2 * m + 1], d1);
            dist[2 * m + 1] = nd1;
            if (nd1 > bv) { bv = nd1; bi = tid + (2 * m + 1) * 256; }
        }

        // warp argmax reduce (lexicographic: max value, then lowest index)
#pragma unroll
        for (int off = 16; off; off >>= 1) {
            float ov = __shfl_down_sync(0xffffffffu, bv, off);
            int   oi = __shfl_down_sync(0xffffffffu, bi, off);
            if (ov > bv || (ov == bv && oi < bi)) { bv = ov; bi = oi; }
        }
        const int pb = s & 1;
        if (lane == 0) { sV[pb][wid] = bv; sI[pb][wid] = bi; }
        __syncthreads();

        // every thread reduces the 8 warp candidates redundantly
        float xv = sV[pb][0];
        int   xi = sI[pb][0];
#pragma unroll
        for (int w = 1; w < 8; w++) {
            float cv = sV[pb][w];
            int   ci = sI[pb][w];
            if (cv > xv || (cv == xv && ci < xi)) { xv = cv; xi = ci; }
        }
        cx = __ldg(P + xi * 3 + 0);   // L1-resident broadcast
        cy = __ldg(P + xi * 3 + 1);
        cz = __ldg(P + xi * 3 + 2);
    }
}

// ---------------------------------------------------------------------------
// Consumer: persistent CTA; each warp loops over items t = s*8+b with stride
// CONS_WARPS, polling the producer progress counter before each item.
// MLP in packed f32x2 (per-lane rn).
// ---------------------------------------------------------------------------
__device__ void bq_mlp_consumer(const float* __restrict__ xyz,
                                const float* __restrict__ w1, const float* __restrict__ b1,
                                const float* __restrict__ w2, const float* __restrict__ b2,
                                const float* __restrict__ w3, const float* __restrict__ b3,
                                float* __restrict__ out, int cta, float* sh)
{
    float* sW1  = sh;                    // 192
    float* sB1  = sW1 + C1 * 3;          // 64
    float* sW2t = sB1 + C1;              // 4096 (transposed: [i][o])
    float* sB2  = sW2t + C2 * C1;        // 64
    float* sW3  = sB2 + C2;              // 8192
    float* sB3  = sW3 + C3 * C2;         // 128
    int*   sNbrAll = (int*)(sB3 + C3);   // 12 warps * 32

    const int tid = threadIdx.x;
    for (int i = tid; i < C1 * 3;  i += CONS_THREADS) sW1[i] = w1[i];
    for (int i = tid; i < C1;      i += CONS_THREADS) sB1[i] = b1[i];
    for (int i = tid; i < C2 * C1; i += CONS_THREADS) {
        int o = i >> 6, ii = i & 63;
        sW2t[ii * C2 + o] = w2[i];
    }
    for (int i = tid; i < C2;      i += CONS_THREADS) sB2[i] = b2[i];
    for (int i = tid; i < C3 * C2; i += CONS_THREADS) sW3[i] = w3[i];
    for (int i = tid; i < C3;      i += CONS_THREADS) sB3[i] = b3[i];
    __syncthreads();

    const int wid  = tid >> 5;
    const int lane = tid & 31;
    int* nb = sNbrAll + wid * KNB;
    const int gw = cta * 12 + wid;       // 0..1667

    for (int t = gw; t < NITEMS; t += CONS_WARPS) {
        const int s = t >> 3;
        const int b = t & 7;
        const float* P = xyz + b * NPTS * 3;

        // wait until center s of batch b is published (backoff poll)
        const int need = s + 1;
        int delay = 64;
        for (;;) {
            int p;
            asm volatile("ld.acquire.gpu.global.s32 %0, [%1];"
                         : "=r"(p) : "l"(&g_prog[b * 32]) : "memory");
            if (p >= need) break;
            __nanosleep(delay);
            if (delay < 2048) delay <<= 1;
        }
        const int cbase = (b * NS + s) * 3;
        const float cx = __ldcg(&g_new_xyz[cbase + 0]);   // L2 read (fresh)
        const float cy = __ldcg(&g_new_xyz[cbase + 1]);
        const float cz = __ldcg(&g_new_xyz[cbase + 2]);

        // ---- ball query: first KNB hits in ascending index order ----
        const float RR = 0.04f;   // JAX weak-typed (0.2*0.2) double -> f32
        int count = 0;
        for (int base = 0; base < NPTS && count < KNB; base += 32) {
            int i = base + lane;
            float dx = cx - P[i * 3 + 0];
            float dy = cy - P[i * 3 + 1];
            float dz = cz - P[i * 3 + 2];
            float d2 = sqdist_xla(dx, dy, dz);
            bool hit = (d2 <= RR);
            unsigned m = __ballot_sync(0xffffffffu, hit);
            int pos = count + __popc(m & ((1u << lane) - 1u));
            if (hit && pos < KNB) nb[pos] = i;
            count += __popc(m);
        }
        __syncwarp();
        int cc = count < KNB ? count : KNB;   // >= 1 always
        if (lane >= cc) nb[lane] = nb[0];     // pad with first hit
        __syncwarp();
        const int ni = nb[lane];

        const float rx = P[ni * 3 + 0] - cx;
        const float ry = P[ni * 3 + 1] - cy;
        const float rz = P[ni * 3 + 2] - cz;

        // ---- layers 1+2 fused, packed f32x2 accumulators (channel pairs) ----
        unsigned long long acc2[C2 / 2];
        {
            const ulonglong2* b2p = reinterpret_cast<const ulonglong2*>(sB2);
#pragma unroll
            for (int j = 0; j < C2 / 4; j++) {
                ulonglong2 v = b2p[j];
                acc2[2 * j] = v.x;
                acc2[2 * j + 1] = v.y;
            }
        }
#pragma unroll 4
        for (int i = 0; i < C1; i++) {
            float a = sB1[i];
            a = fmaf(sW1[i * 3 + 0], rx, a);
            a = fmaf(sW1[i * 3 + 1], ry, a);
            a = fmaf(sW1[i * 3 + 2], rz, a);
            float h1 = fmaxf(a, 0.0f);
            unsigned long long h1p = pack2(h1, h1);
            const ulonglong2* w4 = reinterpret_cast<const ulonglong2*>(sW2t + (i << 6));
#pragma unroll
            for (int j = 0; j < C2 / 4; j++) {
                ulonglong2 w = w4[j];
                acc2[2 * j]     = fma2(w.x, h1p, acc2[2 * j]);
                acc2[2 * j + 1] = fma2(w.y, h1p, acc2[2 * j + 1]);
            }
        }
        // relu (packed via unpack/repack — register halves, no real movs)
#pragma unroll
        for (int j = 0; j < C2 / 2; j++) {
            float a0, a1;
            unpack2(acc2[j], a0, a1);
            acc2[j] = pack2(fmaxf(a0, 0.0f), fmaxf(a1, 0.0f));
        }

        // ---- layer 3: 64 -> 128, packed dot, warp max over 32 neighbors ----
        float* optr = out + BATCH * 3 * NS + (b * C3) * NS + s;
#pragma unroll 2
        for (int o = 0; o < C3; o++) {
            const ulonglong2* w4 = reinterpret_cast<const ulonglong2*>(sW3 + (o << 6));
            unsigned long long a2 = pack2(0.0f, 0.0f);
            unsigned long long a2b = pack2(0.0f, 0.0f);
#pragma unroll
            for (int j = 0; j < C2 / 4; j++) {
                ulonglong2 w = w4[j];
                a2  = fma2(w.x, acc2[2 * j],     a2);
                a2b = fma2(w.y, acc2[2 * j + 1], a2b);
            }
            float p0, p1, q0, q1;
            unpack2(a2, p0, p1);
            unpack2(a2b, q0, q1);
            float a = ((p0 + p1) + (q0 + q1)) + sB3[o];
            a = fmaxf(a, 0.0f);
#pragma unroll
            for (int off = 16; off; off >>= 1)
                a = fmaxf(a, __shfl_xor_sync(0xffffffffu, a, off));
            if (lane == 0) optr[o * NS] = a;
        }
    }
}

// ---------------------------------------------------------------------------
// Fused kernel, 1 CTA per SM (forced by 132KB dynamic smem):
// CTAs 0..7 = FPS producers (dedicated SMs), CTAs 8..146 = persistent consumers.
// ---------------------------------------------------------------------------
__global__ __launch_bounds__(CONS_THREADS) void fused_kernel(
    const float* __restrict__ xyz,
    const float* __restrict__ w1, const float* __restrict__ b1,
    const float* __restrict__ w2, const float* __restrict__ b2,
    const float* __restrict__ w3, const float* __restrict__ b3,
    float* __restrict__ out)
{
    extern __shared__ float sh[];
    if (blockIdx.x < BATCH) {
        if (threadIdx.x >= 256) return;   // whole warps 8..11 exit
        fps_producer(xyz, out, blockIdx.x);
    } else {
        bq_mlp_consumer(xyz, w1, b1, w2, b2, w3, b3, out,
                        blockIdx.x - BATCH, sh);
    }
}

// ---------------------------------------------------------------------------
extern "C" void kernel_launch(void* const* d_in, const int* in_sizes, int n_in,
                              void* d_out, int out_size)
{
    const float* xyz = (const float*)d_in[0];
    // d_in[1] = features, unused by the reference
    const float* w1 = (const float*)d_in[2];
    const float* b1 = (const float*)d_in[3];
    const float* w2 = (const float*)d_in[4];
    const float* b2 = (const float*)d_in[5];
    const float* w3 = (const float*)d_in[6];
    const float* b3 = (const float*)d_in[7];
    float* out = (float*)d_out;

    const int shmem = 132 * 1024;   // forces 1 CTA/SM (228KB / 132KB = 1)
    cudaFuncSetAttribute(fused_kernel, cudaFuncAttributeMaxDynamicSharedMemorySize, shmem);

    reset_kernel<<<1, 32>>>();
    fused_kernel<<<BATCH + NCONS, CONS_THREADS, shmem>>>(xyz, w1, b1, w2, b2, w3, b3, out);
}

// round 6
// speedup vs baseline: 1.0043x; 1.0043x over previous
#include <cuda_runtime.h>

#define BATCH 8
#define NPTS  8192
#define NS    2048      // S = 0.25 * N
#define KNB   32        // nsample
#define C1    64
#define C2    64
#define C3    128

#define NCONS        140                  // consumer CTAs: 8+140 = 148 = full wave
#define CONS_THREADS 384
#define CONS_WARPS   (NCONS * 12)         // 1680
#define NITEMS       (BATCH * NS)         // 16384

// scratch shared between producer (FPS) and consumer (ball-query+MLP) CTAs
__device__ float g_new_xyz[BATCH * NS * 3];
__device__ int   g_prog[BATCH * 32];      // padded: one 128B line per batch

// XLA-exact squared distance: ((dx*dx + dy*dy) + dz*dz), no FMA contraction
__device__ __forceinline__ float sqdist_xla(float dx, float dy, float dz) {
    return __fadd_rn(__fadd_rn(__fmul_rn(dx, dx), __fmul_rn(dy, dy)),
                     __fmul_rn(dz, dz));
}

__device__ __forceinline__ unsigned long long pack2(float a, float b) {
    unsigned long long r;
    asm("mov.b64 %0, {%1, %2};" : "=l"(r) : "f"(a), "f"(b));
    return r;
}
__device__ __forceinline__ void unpack2(unsigned long long v, float& a, float& b) {
    asm("mov.b64 {%0, %1}, %2;" : "=f"(a), "=f"(b) : "l"(v));
}
__device__ __forceinline__ unsigned long long add2(unsigned long long a, unsigned long long b) {
    unsigned long long r;
    asm("add.rn.f32x2 %0, %1, %2;" : "=l"(r) : "l"(a), "l"(b));
    return r;
}
__device__ __forceinline__ unsigned long long mul2(unsigned long long a, unsigned long long b) {
    unsigned long long r;
    asm("mul.rn.f32x2 %0, %1, %2;" : "=l"(r) : "l"(a), "l"(b));
    return r;
}
__device__ __forceinline__ unsigned long long fma2(unsigned long long a, unsigned long long b,
                                                   unsigned long long c) {
    unsigned long long r;
    asm("fma.rn.f32x2 %0, %1, %2, %3;" : "=l"(r) : "l"(a), "l"(b), "l"(c));
    return r;
}

__global__ void reset_kernel() {
    if (threadIdx.x < BATCH) g_prog[threadIdx.x * 32] = 0;
}

// ---------------------------------------------------------------------------
// Producer: farthest point sampling for batch b. Runs on 256 threads (warps
// 8..11 of the CTA have exited). Bit-exact math (f32x2, per-lane rn).
// After writing center s, releases g_prog[b*32] = s+1.
// ---------------------------------------------------------------------------
__device__ void fps_producer(const float* __restrict__ xyz,
                             float* __restrict__ out, int b)
{
    const int tid = threadIdx.x;
    const int lane = tid & 31, wid = tid >> 5;
    const float* P = xyz + b * NPTS * 3;

    __shared__ float sV[2][8];
    __shared__ int   sI[2][8];

    unsigned long long npx[16], npy[16], npz[16];
    float dist[32];
#pragma unroll
    for (int m = 0; m < 16; m++) {
        int i0 = tid + (2 * m) * 256;
        int i1 = tid + (2 * m + 1) * 256;
        npx[m] = pack2(-P[i0 * 3 + 0], -P[i1 * 3 + 0]);
        npy[m] = pack2(-P[i0 * 3 + 1], -P[i1 * 3 + 1]);
        npz[m] = pack2(-P[i0 * 3 + 2], -P[i1 * 3 + 2]);
        dist[2 * m] = 1e10f;
        dist[2 * m + 1] = 1e10f;
    }
    float cx = __ldg(P + 0), cy = __ldg(P + 1), cz = __ldg(P + 2);

    for (int s = 0; s < NS; s++) {
        if (tid == 0) {
            int o = b * 3 * NS + s;          // (B,3,S) transposed output
            out[o]          = cx;
            out[o + NS]     = cy;
            out[o + 2 * NS] = cz;
            int c = (b * NS + s) * 3;
            g_new_xyz[c]     = cx;
            g_new_xyz[c + 1] = cy;
            g_new_xyz[c + 2] = cz;
            // publish: release orders the 6 stores above before the flag
            asm volatile("st.release.gpu.global.s32 [%0], %1;"
                         :: "l"(&g_prog[b * 32]), "r"(s + 1) : "memory");
        }

        const unsigned long long cxx = pack2(cx, cx);
        const unsigned long long cyy = pack2(cy, cy);
        const unsigned long long czz = pack2(cz, cz);

        float bv = -1.0f;
        int   bi = 0;
#pragma unroll
        for (int m = 0; m < 16; m++) {
            unsigned long long dx2 = add2(cxx, npx[m]);   // cx - px (exact)
            unsigned long long dy2 = add2(cyy, npy[m]);
            unsigned long long dz2 = add2(czz, npz[m]);
            unsigned long long d2p = add2(add2(mul2(dx2, dx2), mul2(dy2, dy2)),
                                          mul2(dz2, dz2)); // ((x²+y²)+z²) rn
            float d0, d1;
            unpack2(d2p, d0, d1);
            float nd0 = fminf(dist[2 * m], d0);
            dist[2 * m] = nd0;
            if (nd0 > bv) { bv = nd0; bi = tid + (2 * m) * 256; }
            float nd1 = fminf(dist[2 * m + 1], d1);
            dist[2 * m + 1] = nd1;
            if (nd1 > bv) { bv = nd1; bi = tid + (2 * m + 1) * 256; }
        }

        // warp argmax reduce (lexicographic: max value, then lowest index)
#pragma unroll
        for (int off = 16; off; off >>= 1) {
            float ov = __shfl_down_sync(0xffffffffu, bv, off);
            int   oi = __shfl_down_sync(0xffffffffu, bi, off);
            if (ov > bv || (ov == bv && oi < bi)) { bv = ov; bi = oi; }
        }
        const int pb = s & 1;
        if (lane == 0) { sV[pb][wid] = bv; sI[pb][wid] = bi; }
        __syncthreads();

        // every thread reduces the 8 warp candidates redundantly
        float xv = sV[pb][0];
        int   xi = sI[pb][0];
#pragma unroll
        for (int w = 1; w < 8; w++) {
            float cv = sV[pb][w];
            int   ci = sI[pb][w];
            if (cv > xv || (cv == xv && ci < xi)) { xv = cv; xi = ci; }
        }
        cx = __ldg(P + xi * 3 + 0);   // L1-resident broadcast
        cy = __ldg(P + xi * 3 + 1);
        cz = __ldg(P + xi * 3 + 2);
    }
}

// ---------------------------------------------------------------------------
// Consumer: persistent CTA; each warp loops over items t = s*8+b with stride
// CONS_WARPS, polling the producer progress counter before each item.
// MLP in packed f32x2 (per-lane rn).
// ---------------------------------------------------------------------------
__device__ void bq_mlp_consumer(const float* __restrict__ xyz,
                                const float* __restrict__ w1, const float* __restrict__ b1,
                                const float* __restrict__ w2, const float* __restrict__ b2,
                                const float* __restrict__ w3, const float* __restrict__ b3,
                                float* __restrict__ out, int cta, float* sh)
{
    float* sW1  = sh;                    // 192
    float* sB1  = sW1 + C1 * 3;          // 64
    float* sW2t = sB1 + C1;              // 4096 (transposed: [i][o])
    float* sB2  = sW2t + C2 * C1;        // 64
    float* sW3  = sB2 + C2;              // 8192
    float* sB3  = sW3 + C3 * C2;         // 128
    int*   sNbrAll = (int*)(sB3 + C3);   // 12 warps * 32

    const int tid = threadIdx.x;
    for (int i = tid; i < C1 * 3;  i += CONS_THREADS) sW1[i] = w1[i];
    for (int i = tid; i < C1;      i += CONS_THREADS) sB1[i] = b1[i];
    for (int i = tid; i < C2 * C1; i += CONS_THREADS) {
        int o = i >> 6, ii = i & 63;
        sW2t[ii * C2 + o] = w2[i];
    }
    for (int i = tid; i < C2;      i += CONS_THREADS) sB2[i] = b2[i];
    for (int i = tid; i < C3 * C2; i += CONS_THREADS) sW3[i] = w3[i];
    for (int i = tid; i < C3;      i += CONS_THREADS) sB3[i] = b3[i];
    __syncthreads();

    const int wid  = tid >> 5;
    const int lane = tid & 31;
    int* nb = sNbrAll + wid * KNB;
    const int gw = cta * 12 + wid;       // 0..1679

    for (int t = gw; t < NITEMS; t += CONS_WARPS) {
        const int s = t >> 3;
        const int b = t & 7;
        const float* P = xyz + b * NPTS * 3;

        // wait until center s of batch b is published (backoff poll,
        // generous floor to keep spin power low while producers run)
        const int need = s + 1;
        int delay = 256;
        for (;;) {
            int p;
            asm volatile("ld.acquire.gpu.global.s32 %0, [%1];"
                         : "=r"(p) : "l"(&g_prog[b * 32]) : "memory");
            if (p >= need) break;
            __nanosleep(delay);
            if (delay < 4096) delay <<= 1;
        }
        const int cbase = (b * NS + s) * 3;
        const float cx = __ldcg(&g_new_xyz[cbase + 0]);   // L2 read (fresh)
        const float cy = __ldcg(&g_new_xyz[cbase + 1]);
        const float cz = __ldcg(&g_new_xyz[cbase + 2]);

        // ---- ball query: first KNB hits in ascending index order ----
        const float RR = 0.04f;   // JAX weak-typed (0.2*0.2) double -> f32
        int count = 0;
        for (int base = 0; base < NPTS && count < KNB; base += 32) {
            int i = base + lane;
            float dx = cx - P[i * 3 + 0];
            float dy = cy - P[i * 3 + 1];
            float dz = cz - P[i * 3 + 2];
            float d2 = sqdist_xla(dx, dy, dz);
            bool hit = (d2 <= RR);
            unsigned m = __ballot_sync(0xffffffffu, hit);
            int pos = count + __popc(m & ((1u << lane) - 1u));
            if (hit && pos < KNB) nb[pos] = i;
            count += __popc(m);
        }
        __syncwarp();
        int cc = count < KNB ? count : KNB;   // >= 1 always
        if (lane >= cc) nb[lane] = nb[0];     // pad with first hit
        __syncwarp();
        const int ni = nb[lane];

        const float rx = P[ni * 3 + 0] - cx;
        const float ry = P[ni * 3 + 1] - cy;
        const float rz = P[ni * 3 + 2] - cz;

        // ---- layers 1+2 fused, packed f32x2 accumulators (channel pairs) ----
        unsigned long long acc2[C2 / 2];
        {
            const ulonglong2* b2p = reinterpret_cast<const ulonglong2*>(sB2);
#pragma unroll
            for (int j = 0; j < C2 / 4; j++) {
                ulonglong2 v = b2p[j];
                acc2[2 * j] = v.x;
                acc2[2 * j + 1] = v.y;
            }
        }
#pragma unroll 4
        for (int i = 0; i < C1; i++) {
            float a = sB1[i];
            a = fmaf(sW1[i * 3 + 0], rx, a);
            a = fmaf(sW1[i * 3 + 1], ry, a);
            a = fmaf(sW1[i * 3 + 2], rz, a);
            float h1 = fmaxf(a, 0.0f);
            unsigned long long h1p = pack2(h1, h1);
            const ulonglong2* w4 = reinterpret_cast<const ulonglong2*>(sW2t + (i << 6));
#pragma unroll
            for (int j = 0; j < C2 / 4; j++) {
                ulonglong2 w = w4[j];
                acc2[2 * j]     = fma2(w.x, h1p, acc2[2 * j]);
                acc2[2 * j + 1] = fma2(w.y, h1p, acc2[2 * j + 1]);
            }
        }
        // relu (packed via unpack/repack — register halves, no real movs)
#pragma unroll
        for (int j = 0; j < C2 / 2; j++) {
            float a0, a1;
            unpack2(acc2[j], a0, a1);
            acc2[j] = pack2(fmaxf(a0, 0.0f), fmaxf(a1, 0.0f));
        }

        // ---- layer 3: 64 -> 128, packed dot, warp max over 32 neighbors ----
        float* optr = out + BATCH * 3 * NS + (b * C3) * NS + s;
#pragma unroll 2
        for (int o = 0; o < C3; o++) {
            const ulonglong2* w4 = reinterpret_cast<const ulonglong2*>(sW3 + (o << 6));
            unsigned long long a2 = pack2(0.0f, 0.0f);
            unsigned long long a2b = pack2(0.0f, 0.0f);
#pragma unroll
            for (int j = 0; j < C2 / 4; j++) {
                ulonglong2 w = w4[j];
                a2  = fma2(w.x, acc2[2 * j],     a2);
                a2b = fma2(w.y, acc2[2 * j + 1], a2b);
            }
            float p0, p1, q0, q1;
            unpack2(a2, p0, p1);
            unpack2(a2b, q0, q1);
            float a = ((p0 + p1) + (q0 + q1)) + sB3[o];
            a = fmaxf(a, 0.0f);
#pragma unroll
            for (int off = 16; off; off >>= 1)
                a = fmaxf(a, __shfl_xor_sync(0xffffffffu, a, off));
            if (lane == 0) optr[o * NS] = a;
        }
    }
}

// ---------------------------------------------------------------------------
// Fused kernel, 1 CTA per SM (forced by 132KB dynamic smem), grid = 148
// (>= 148 avoids the sm_103a low-grid issue throttle on large kernel bodies):
// CTAs 0..7 = FPS producers (dedicated SMs), CTAs 8..147 = persistent consumers.
// ---------------------------------------------------------------------------
__global__ __launch_bounds__(CONS_THREADS) void fused_kernel(
    const float* __restrict__ xyz,
    const float* __restrict__ w1, const float* __restrict__ b1,
    const float* __restrict__ w2, const float* __restrict__ b2,
    const float* __restrict__ w3, const float* __restrict__ b3,
    float* __restrict__ out)
{
    extern __shared__ float sh[];
    if (blockIdx.x < BATCH) {
        if (threadIdx.x >= 256) return;   // whole warps 8..11 exit
        fps_producer(xyz, out, blockIdx.x);
    } else {
        bq_mlp_consumer(xyz, w1, b1, w2, b2, w3, b3, out,
                        blockIdx.x - BATCH, sh);
    }
}

// ---------------------------------------------------------------------------
extern "C" void kernel_launch(void* const* d_in, const int* in_sizes, int n_in,
                              void* d_out, int out_size)
{
    const float* xyz = (const float*)d_in[0];
    // d_in[1] = features, unused by the reference
    const float* w1 = (const float*)d_in[2];
    const float* b1 = (const float*)d_in[3];
    const float* w2 = (const float*)d_in[4];
    const float* b2 = (const float*)d_in[5];
    const float* w3 = (const float*)d_in[6];
    const float* b3 = (const float*)d_in[7];
    float* out = (float*)d_out;

    const int shmem = 132 * 1024;   // forces 1 CTA/SM (228KB / 132KB = 1)
    cudaFuncSetAttribute(fused_kernel, cudaFuncAttributeMaxDynamicSharedMemorySize, shmem);

    reset_kernel<<<1, 32>>>();
    fused_kernel<<<BATCH + NCONS, CONS_THREADS, shmem>>>(xyz, w1, b1, w2, b2, w3, b3, out);
}

// round 7
// speedup vs baseline: 1.4491x; 1.4429x over previous
#include <cuda_runtime.h>

#define BATCH 8
#define NPTS  8192
#define NS    2048      // S = 0.25 * N
#define KNB   32        // nsample
#define C1    64
#define C2    64
#define C3    128

// scratch: new_xyz coords shared between the two kernels
__device__ float g_new_xyz[BATCH * NS * 3];

// XLA-exact squared distance: ((dx*dx + dy*dy) + dz*dz), no FMA contraction
__device__ __forceinline__ float sqdist_xla(float dx, float dy, float dz) {
    return __fadd_rn(__fadd_rn(__fmul_rn(dx, dx), __fmul_rn(dy, dy)),
                     __fmul_rn(dz, dz));
}

__device__ __forceinline__ unsigned long long pack2(float a, float b) {
    unsigned long long r;
    asm("mov.b64 %0, {%1, %2};" : "=l"(r) : "f"(a), "f"(b));
    return r;
}
__device__ __forceinline__ void unpack2(unsigned long long v, float& a, float& b) {
    asm("mov.b64 {%0, %1}, %2;" : "=f"(a), "=f"(b) : "l"(v));
}
__device__ __forceinline__ unsigned long long add2(unsigned long long a, unsigned long long b) {
    unsigned long long r;
    asm("add.rn.f32x2 %0, %1, %2;" : "=l"(r) : "l"(a), "l"(b));
    return r;
}
__device__ __forceinline__ unsigned long long mul2(unsigned long long a, unsigned long long b) {
    unsigned long long r;
    asm("mul.rn.f32x2 %0, %1, %2;" : "=l"(r) : "l"(a), "l"(b));
    return r;
}
__device__ __forceinline__ unsigned long long fma2(unsigned long long a, unsigned long long b,
                                                   unsigned long long c) {
    unsigned long long r;
    asm("fma.rn.f32x2 %0, %1, %2, %3;" : "=l"(r) : "l"(a), "l"(b), "l"(c));
    return r;
}

// ---------------------------------------------------------------------------
// Kernel 1: farthest point sampling. One CTA (256 threads) per batch.
// Per iteration:
//   phase A: f32x2 dist update (bit-exact rn), per-thread tree-fmax,
//            warp max via REDUX.SYNC (float bits, all dists >= 0),
//            leaders post to smem, block max computed by every thread.
//   phase B: only warps matching block max scan for the lowest matching
//            global index (tree-min + REDUX.MIN + smem atomicMin) ->
//            exact jnp.argmax first-occurrence tie semantics.
// ---------------------------------------------------------------------------
__global__ __launch_bounds__(256) void fps_kernel(const float* __restrict__ xyz,
                                                  float* __restrict__ out)
{
    const int b   = blockIdx.x;
    const int tid = threadIdx.x;
    const int lane = tid & 31, wid = tid >> 5;
    const float* P = xyz + b * NPTS * 3;

    __shared__ int sVal[2][8];   // per-warp max (float bits)
    __shared__ int sIdx[2];      // block argmin index (atomicMin target)

    unsigned long long npx[16], npy[16], npz[16];
    float dist[32];
#pragma unroll
    for (int m = 0; m < 16; m++) {
        int i0 = tid + (2 * m) * 256;
        int i1 = tid + (2 * m + 1) * 256;
        npx[m] = pack2(-P[i0 * 3 + 0], -P[i1 * 3 + 0]);
        npy[m] = pack2(-P[i0 * 3 + 1], -P[i1 * 3 + 1]);
        npz[m] = pack2(-P[i0 * 3 + 2], -P[i1 * 3 + 2]);
        dist[2 * m] = 1e10f;
        dist[2 * m + 1] = 1e10f;
    }
    float cx = __ldg(P + 0), cy = __ldg(P + 1), cz = __ldg(P + 2);

    for (int s = 0; s < NS; s++) {
        const int pb = s & 1;
        if (tid == 0) {
            int o = b * 3 * NS + s;          // (B,3,S) transposed output
            out[o]          = cx;
            out[o + NS]     = cy;
            out[o + 2 * NS] = cz;
            int c = (b * NS + s) * 3;
            g_new_xyz[c]     = cx;
            g_new_xyz[c + 1] = cy;
            g_new_xyz[c + 2] = cz;
            sIdx[pb] = 0x7FFFFFFF;
        }

        const unsigned long long cxx = pack2(cx, cx);
        const unsigned long long cyy = pack2(cy, cy);
        const unsigned long long czz = pack2(cz, cz);

        // ---- dist update (bit-exact, no index tracking) ----
#pragma unroll
        for (int m = 0; m < 16; m++) {
            unsigned long long dx2 = add2(cxx, npx[m]);   // cx - px (exact)
            unsigned long long dy2 = add2(cyy, npy[m]);
            unsigned long long dz2 = add2(czz, npz[m]);
            unsigned long long d2p = add2(add2(mul2(dx2, dx2), mul2(dy2, dy2)),
                                          mul2(dz2, dz2)); // ((x²+y²)+z²) rn
            float d0, d1;
            unpack2(d2p, d0, d1);
            dist[2 * m]     = fminf(dist[2 * m], d0);
            dist[2 * m + 1] = fminf(dist[2 * m + 1], d1);
        }

        // ---- per-thread tree max (depth 5) ----
        float t[16];
#pragma unroll
        for (int j = 0; j < 16; j++) t[j] = fmaxf(dist[j], dist[j + 16]);
#pragma unroll
        for (int st = 8; st; st >>= 1)
#pragma unroll
            for (int j = 0; j < 8; j++)
                if (j < st) t[j] = fmaxf(t[j], t[j + st]);
        // warp max: all dists >= 0 -> float bits are int-monotone
        const int wmaxi = __reduce_max_sync(0xffffffffu, __float_as_int(t[0]));

        if (lane == 0) sVal[pb][wid] = wmaxi;
        __syncthreads();

        // block max (every thread, 8 slots)
        int bmax = sVal[pb][0];
#pragma unroll
        for (int w = 1; w < 8; w++) bmax = max(bmax, sVal[pb][w]);

        // ---- phase B: only matching warps recover the lowest index ----
        if (wmaxi == bmax) {
            int c[16];
#pragma unroll
            for (int j = 0; j < 16; j++) {
                int c0 = (__float_as_int(dist[j])      == bmax) ? (j * 256 + tid)        : 0x7FFFFFFF;
                int c1 = (__float_as_int(dist[j + 16]) == bmax) ? ((j + 16) * 256 + tid) : 0x7FFFFFFF;
                c[j] = min(c0, c1);
            }
#pragma unroll
            for (int st = 8; st; st >>= 1)
#pragma unroll
                for (int j = 0; j < 8; j++)
                    if (j < st) c[j] = min(c[j], c[j + st]);
            int wmin = __reduce_min_sync(0xffffffffu, c[0]);
            if (lane == 0) atomicMin(&sIdx[pb], wmin);
        }
        __syncthreads();

        const int xi = sIdx[pb];
        cx = __ldg(P + xi * 3 + 0);   // L1-resident broadcast
        cy = __ldg(P + xi * 3 + 1);
        cz = __ldg(P + xi * 3 + 2);
    }
}

// ---------------------------------------------------------------------------
// Kernel 2: fused ball-query + grouping + 3-layer MLP + max-pool.
// One warp per center (lane = neighbor). MLP in packed f32x2 (per-lane rn).
// 4 CTAs / SM (51KB smem each).
// ---------------------------------------------------------------------------
__global__ __launch_bounds__(128, 4) void bq_mlp_kernel(
    const float* __restrict__ xyz,
    const float* __restrict__ w1, const float* __restrict__ b1,
    const float* __restrict__ w2, const float* __restrict__ b2,
    const float* __restrict__ w3, const float* __restrict__ b3,
    float* __restrict__ out)
{
    extern __shared__ float sh[];
    float* sW1  = sh;                    // 192
    float* sB1  = sW1 + C1 * 3;          // 64
    float* sW2t = sB1 + C1;              // 4096 (transposed: [i][o])
    float* sB2  = sW2t + C2 * C1;        // 64
    float* sW3  = sB2 + C2;              // 8192
    float* sB3  = sW3 + C3 * C2;         // 128
    int*   sNbrAll = (int*)(sB3 + C3);   // 4 warps * 32

    const int tid = threadIdx.x;
    for (int i = tid; i < C1 * 3;  i += 128) sW1[i] = w1[i];
    for (int i = tid; i < C1;      i += 128) sB1[i] = b1[i];
    for (int i = tid; i < C2 * C1; i += 128) {
        int o = i >> 6, ii = i & 63;
        sW2t[ii * C2 + o] = w2[i];
    }
    for (int i = tid; i < C2;      i += 128) sB2[i] = b2[i];
    for (int i = tid; i < C3 * C2; i += 128) sW3[i] = w3[i];
    for (int i = tid; i < C3;      i += 128) sB3[i] = b3[i];
    __syncthreads();

    const int wid  = tid >> 5;
    const int lane = tid & 31;
    const int c    = blockIdx.x * 4 + wid;      // center id, 0..16383
    const int b    = c >> 11;                   // / NS
    const int s    = c & (NS - 1);
    const float* P = xyz + b * NPTS * 3;

    const float cx = g_new_xyz[c * 3 + 0];
    const float cy = g_new_xyz[c * 3 + 1];
    const float cz = g_new_xyz[c * 3 + 2];

    // ---- ball query: first KNB hits in ascending index order ----
    const float RR = 0.04f;   // JAX weak-typed (0.2*0.2) double -> f32
    int count = 0;
    int* nb = sNbrAll + wid * KNB;
    for (int base = 0; base < NPTS && count < KNB; base += 32) {
        int i = base + lane;
        float dx = cx - P[i * 3 + 0];
        float dy = cy - P[i * 3 + 1];
        float dz = cz - P[i * 3 + 2];
        float d2 = sqdist_xla(dx, dy, dz);
        bool hit = (d2 <= RR);
        unsigned m = __ballot_sync(0xffffffffu, hit);
        int pos = count + __popc(m & ((1u << lane) - 1u));
        if (hit && pos < KNB) nb[pos] = i;
        count += __popc(m);
    }
    __syncwarp();
    int cc = count < KNB ? count : KNB;   // >= 1 always
    if (lane >= cc) nb[lane] = nb[0];     // pad with first hit
    __syncwarp();
    const int ni = nb[lane];

    const float rx = P[ni * 3 + 0] - cx;
    const float ry = P[ni * 3 + 1] - cy;
    const float rz = P[ni * 3 + 2] - cz;

    // ---- layers 1+2 fused, packed f32x2 accumulators (channel pairs) ----
    unsigned long long acc2[C2 / 2];
    {
        const ulonglong2* b2p = reinterpret_cast<const ulonglong2*>(sB2);
#pragma unroll
        for (int j = 0; j < C2 / 4; j++) {
            ulonglong2 v = b2p[j];
            acc2[2 * j] = v.x;
            acc2[2 * j + 1] = v.y;
        }
    }
#pragma unroll 4
    for (int i = 0; i < C1; i++) {
        float a = sB1[i];
        a = fmaf(sW1[i * 3 + 0], rx, a);
        a = fmaf(sW1[i * 3 + 1], ry, a);
        a = fmaf(sW1[i * 3 + 2], rz, a);
        float h1 = fmaxf(a, 0.0f);
        unsigned long long h1p = pack2(h1, h1);
        const ulonglong2* w4 = reinterpret_cast<const ulonglong2*>(sW2t + (i << 6));
#pragma unroll
        for (int j = 0; j < C2 / 4; j++) {
            ulonglong2 w = w4[j];
            acc2[2 * j]     = fma2(w.x, h1p, acc2[2 * j]);
            acc2[2 * j + 1] = fma2(w.y, h1p, acc2[2 * j + 1]);
        }
    }
    // relu (packed via unpack/repack — register halves, no real movs)
#pragma unroll
    for (int j = 0; j < C2 / 2; j++) {
        float a0, a1;
        unpack2(acc2[j], a0, a1);
        acc2[j] = pack2(fmaxf(a0, 0.0f), fmaxf(a1, 0.0f));
    }

    // ---- layer 3: 64 -> 128, packed dot, warp max over 32 neighbors ----
    float* optr = out + BATCH * 3 * NS + (b * C3) * NS + s;
#pragma unroll 2
    for (int o = 0; o < C3; o++) {
        const ulonglong2* w4 = reinterpret_cast<const ulonglong2*>(sW3 + (o << 6));
        unsigned long long a2  = pack2(0.0f, 0.0f);
        unsigned long long a2b = pack2(0.0f, 0.0f);
#pragma unroll
        for (int j = 0; j < C2 / 4; j++) {
            ulonglong2 w = w4[j];
            a2  = fma2(w.x, acc2[2 * j],     a2);
            a2b = fma2(w.y, acc2[2 * j + 1], a2b);
        }
        float p0, p1, q0, q1;
        unpack2(a2, p0, p1);
        unpack2(a2b, q0, q1);
        float a = ((p0 + p1) + (q0 + q1)) + sB3[o];
        a = fmaxf(a, 0.0f);
#pragma unroll
        for (int off = 16; off; off >>= 1)
            a = fmaxf(a, __shfl_xor_sync(0xffffffffu, a, off));
        if (lane == 0) optr[o * NS] = a;
    }
}

// ---------------------------------------------------------------------------
extern "C" void kernel_launch(void* const* d_in, const int* in_sizes, int n_in,
                              void* d_out, int out_size)
{
    const float* xyz = (const float*)d_in[0];
    // d_in[1] = features, unused by the reference
    const float* w1 = (const float*)d_in[2];
    const float* b1 = (const float*)d_in[3];
    const float* w2 = (const float*)d_in[4];
    const float* b2 = (const float*)d_in[5];
    const float* w3 = (const float*)d_in[6];
    const float* b3 = (const float*)d_in[7];
    float* out = (float*)d_out;

    const int shmem = (C1 * 3 + C1 + C2 * C1 + C2 + C3 * C2 + C3) * 4 + 4 * KNB * 4;
    cudaFuncSetAttribute(bq_mlp_kernel, cudaFuncAttributeMaxDynamicSharedMemorySize, shmem);

    fps_kernel<<<BATCH, 256>>>(xyz, out);
    bq_mlp_kernel<<<(BATCH * NS) / 4, 128, shmem>>>(xyz, w1, b1, w2, b2, w3, b3, out);
}